// round 16
// baseline (speedup 1.0000x reference)
#include <cuda_runtime.h>
#include <stdint.h>

// Problem constants (match reference: B=1048576, Z_DIM=128, K=512)
#define ZDIM 128
#define KDIM 512
#define ROWS_PER_WARP 8

// Scratch for transposed a: at[k][d] = a[d][k].  512*128 floats = 256 KB.
__device__ float g_at[KDIM * ZDIM];

// ---------------------------------------------------------------------------
// Pre-pass: 32x32 smem-tiled transpose, coalesced both directions.
// Fires programmatic-launch-completion so the main kernel overlaps with it.
// ---------------------------------------------------------------------------
__global__ void transpose_a_kernel(const float* __restrict__ a) {
    __shared__ float tile[32][33];
    int kBase = blockIdx.x * 32;
    int dBase = blockIdx.y * 32;
    #pragma unroll
    for (int r = 0; r < 32; r += 8) {
        int d = dBase + threadIdx.y + r;
        int k = kBase + threadIdx.x;
        tile[threadIdx.y + r][threadIdx.x] = a[d * KDIM + k];
    }
    __syncthreads();
    #pragma unroll
    for (int r = 0; r < 32; r += 8) {
        int k = kBase + threadIdx.y + r;
        int d = dBase + threadIdx.x;
        g_at[k * ZDIM + d] = tile[threadIdx.x][threadIdx.y + r];
    }
#if __CUDA_ARCH__ >= 900
    cudaTriggerProgrammaticLaunchCompletion();
#endif
}

// ---------------------------------------------------------------------------
// Main kernel (PDL consumer) — session optimum, FINAL FORM:
//   - warp handles 8 rows (32 lanes x float4 = one 512B row, perfectly
//     coalesced loads and stores)
//   - occupancy 3 (regs 77): past the latency-hiding knee; higher occupancy
//     measured neutral-to-worse under PDL (sync-burst spike at occ 8)
//   - idx/scale/z front-batched BEFORE cudaGridDependencySynchronize so the
//     transpose kernel hides entirely under their load latency
//   - z loads .cs, out stores .cs (streaming eviction; keeps the 256KB
//     gather table + idx/scale metadata L2-resident -> gather is 100% L2-hit,
//     zero DRAM read amplification)
// DRAM traffic is exactly minimal (1.0326 GB). Measured at 6.66-6.70 TB/s,
// the GB300 mixed 1:1 read/write HBM controller ceiling (~84% of spec);
// insensitive to occupancy, MLP depth, cache policy, and launch structure
// across 11 profiled configurations.
// ---------------------------------------------------------------------------
__global__ void __launch_bounds__(256, 3)
fused_gather_axpy_kernel(const float4* __restrict__ z4,
                         const int* __restrict__ labels_idx,
                         const float* __restrict__ labels_scale,
                         float4* __restrict__ out4,
                         int n_rows) {
    const int lane   = threadIdx.x & 31;
    const int warp_g = blockIdx.x * (blockDim.x >> 5) + (threadIdx.x >> 5);
    const int row0   = warp_g * ROWS_PER_WARP;

    const bool full = (row0 + ROWS_PER_WARP <= n_rows);

    int    idx[ROWS_PER_WARP];
    float  scl[ROWS_PER_WARP];
    float4 zv[ROWS_PER_WARP];
    const size_t base = (size_t)row0 * (ZDIM / 4) + lane;

    if (full) {
        #pragma unroll
        for (int r = 0; r < ROWS_PER_WARP; ++r) idx[r] = __ldg(&labels_idx[row0 + r]);
        #pragma unroll
        for (int r = 0; r < ROWS_PER_WARP; ++r) scl[r] = __ldg(&labels_scale[row0 + r]);
        #pragma unroll
        for (int r = 0; r < ROWS_PER_WARP; ++r)
            zv[r] = __ldcs(&z4[base + (size_t)r * (ZDIM / 4)]);
    }

#if __CUDA_ARCH__ >= 900
    cudaGridDependencySynchronize();   // wait for transpose (g_at ready)
#endif

    const float4* __restrict__ at4 = reinterpret_cast<const float4*>(g_at);

    if (full) {
        float4 av[ROWS_PER_WARP];
        #pragma unroll
        for (int r = 0; r < ROWS_PER_WARP; ++r)
            av[r] = __ldg(&at4[(size_t)idx[r] * (ZDIM / 4) + lane]);

        #pragma unroll
        for (int r = 0; r < ROWS_PER_WARP; ++r) {
            float4 o;
            o.x = fmaf(av[r].x, scl[r], zv[r].x);
            o.y = fmaf(av[r].y, scl[r], zv[r].y);
            o.z = fmaf(av[r].z, scl[r], zv[r].z);
            o.w = fmaf(av[r].w, scl[r], zv[r].w);
            __stcs(&out4[base + (size_t)r * (ZDIM / 4)], o);
        }
    } else if (row0 < n_rows) {
        for (int r = row0; r < n_rows; ++r) {
            int   i = __ldg(&labels_idx[r]);
            float s = __ldg(&labels_scale[r]);
            size_t off = (size_t)r * (ZDIM / 4) + lane;
            float4 zvv = __ldcs(&z4[off]);
            float4 avv = __ldg(&at4[(size_t)i * (ZDIM / 4) + lane]);
            float4 o;
            o.x = fmaf(avv.x, s, zvv.x);
            o.y = fmaf(avv.y, s, zvv.y);
            o.z = fmaf(avv.z, s, zvv.z);
            o.w = fmaf(avv.w, s, zvv.w);
            __stcs(&out4[off], o);
        }
    }
}

extern "C" void kernel_launch(void* const* d_in, const int* in_sizes, int n_in,
                              void* d_out, int out_size) {
    const float* z     = (const float*)d_in[0];   // (B, 128) f32
    const float* a     = (const float*)d_in[1];   // (128, 512) f32
    const int*   idx   = (const int*)d_in[2];     // (B,) int32 on device
    const float* scale = (const float*)d_in[3];   // (B,) f32
    float*       out   = (float*)d_out;

    const int B = in_sizes[2];

    // 1) transpose a into L2-resident scratch (PDL producer)
    {
        dim3 grid(KDIM / 32, ZDIM / 32);   // (16, 4)
        dim3 block(32, 8);
        transpose_a_kernel<<<grid, block>>>(a);
    }

    // 2) fused gather + axpy, PDL consumer (overlaps the transpose)
    {
        int warps_per_block = 256 / 32;
        int rows_per_block  = warps_per_block * ROWS_PER_WARP;   // 64
        int blocks = (B + rows_per_block - 1) / rows_per_block;  // 16384

        cudaLaunchConfig_t cfg = {};
        cfg.gridDim  = dim3(blocks, 1, 1);
        cfg.blockDim = dim3(256, 1, 1);
        cfg.dynamicSmemBytes = 0;
        cfg.stream = 0;

        cudaLaunchAttribute attrs[1];
        attrs[0].id = cudaLaunchAttributeProgrammaticStreamSerialization;
        attrs[0].val.programmaticStreamSerializationAllowed = 1;
        cfg.attrs = attrs;
        cfg.numAttrs = 1;

        cudaLaunchKernelEx(&cfg, fused_gather_axpy_kernel,
                           (const float4*)z, idx, scale, (float4*)out, B);
    }
}

// round 17
// speedup vs baseline: 1.0008x; 1.0008x over previous
#include <cuda_runtime.h>
#include <stdint.h>

// Problem constants (match reference: B=1048576, Z_DIM=128, K=512)
#define ZDIM 128
#define KDIM 512
#define ROWS_PER_WARP 8

// Scratch for transposed a: at[k][d] = a[d][k].  512*128 floats = 256 KB.
__device__ float g_at[KDIM * ZDIM];

// ---------------------------------------------------------------------------
// Pre-pass: 32x32 smem-tiled transpose, coalesced both directions.
// Fires programmatic-launch-completion so the main kernel overlaps with it.
// ---------------------------------------------------------------------------
__global__ void transpose_a_kernel(const float* __restrict__ a) {
    __shared__ float tile[32][33];
    int kBase = blockIdx.x * 32;
    int dBase = blockIdx.y * 32;
    #pragma unroll
    for (int r = 0; r < 32; r += 8) {
        int d = dBase + threadIdx.y + r;
        int k = kBase + threadIdx.x;
        tile[threadIdx.y + r][threadIdx.x] = a[d * KDIM + k];
    }
    __syncthreads();
    #pragma unroll
    for (int r = 0; r < 32; r += 8) {
        int k = kBase + threadIdx.y + r;
        int d = dBase + threadIdx.x;
        g_at[k * ZDIM + d] = tile[threadIdx.x][threadIdx.y + r];
    }
#if __CUDA_ARCH__ >= 900
    cudaTriggerProgrammaticLaunchCompletion();
#endif
}

// ---------------------------------------------------------------------------
// Main kernel (PDL consumer) — session optimum, FINAL FORM:
//   - warp handles 8 rows (32 lanes x float4 = one 512B row, perfectly
//     coalesced loads and stores)
//   - occupancy 3 (regs 77): past the latency-hiding knee; higher occupancy
//     measured neutral-to-worse under PDL (sync-burst spike at occ 8)
//   - idx/scale/z front-batched BEFORE cudaGridDependencySynchronize so the
//     transpose kernel hides entirely under their load latency
//   - z loads .cs, out stores .cs (streaming eviction; keeps the 256KB
//     gather table + idx/scale metadata L2-resident -> gather is 100% L2-hit,
//     zero DRAM read amplification)
// DRAM traffic is exactly minimal (1.0326 GB). Measured at 6.66-6.70 TB/s,
// the GB300 mixed 1:1 read/write HBM controller ceiling (~84% of spec);
// insensitive to occupancy, MLP depth, cache policy, and launch structure
// across 11 profiled configurations.
// ---------------------------------------------------------------------------
__global__ void __launch_bounds__(256, 3)
fused_gather_axpy_kernel(const float4* __restrict__ z4,
                         const int* __restrict__ labels_idx,
                         const float* __restrict__ labels_scale,
                         float4* __restrict__ out4,
                         int n_rows) {
    const int lane   = threadIdx.x & 31;
    const int warp_g = blockIdx.x * (blockDim.x >> 5) + (threadIdx.x >> 5);
    const int row0   = warp_g * ROWS_PER_WARP;

    const bool full = (row0 + ROWS_PER_WARP <= n_rows);

    int    idx[ROWS_PER_WARP];
    float  scl[ROWS_PER_WARP];
    float4 zv[ROWS_PER_WARP];
    const size_t base = (size_t)row0 * (ZDIM / 4) + lane;

    if (full) {
        #pragma unroll
        for (int r = 0; r < ROWS_PER_WARP; ++r) idx[r] = __ldg(&labels_idx[row0 + r]);
        #pragma unroll
        for (int r = 0; r < ROWS_PER_WARP; ++r) scl[r] = __ldg(&labels_scale[row0 + r]);
        #pragma unroll
        for (int r = 0; r < ROWS_PER_WARP; ++r)
            zv[r] = __ldcs(&z4[base + (size_t)r * (ZDIM / 4)]);
    }

#if __CUDA_ARCH__ >= 900
    cudaGridDependencySynchronize();   // wait for transpose (g_at ready)
#endif

    const float4* __restrict__ at4 = reinterpret_cast<const float4*>(g_at);

    if (full) {
        float4 av[ROWS_PER_WARP];
        #pragma unroll
        for (int r = 0; r < ROWS_PER_WARP; ++r)
            av[r] = __ldg(&at4[(size_t)idx[r] * (ZDIM / 4) + lane]);

        #pragma unroll
        for (int r = 0; r < ROWS_PER_WARP; ++r) {
            float4 o;
            o.x = fmaf(av[r].x, scl[r], zv[r].x);
            o.y = fmaf(av[r].y, scl[r], zv[r].y);
            o.z = fmaf(av[r].z, scl[r], zv[r].z);
            o.w = fmaf(av[r].w, scl[r], zv[r].w);
            __stcs(&out4[base + (size_t)r * (ZDIM / 4)], o);
        }
    } else if (row0 < n_rows) {
        for (int r = row0; r < n_rows; ++r) {
            int   i = __ldg(&labels_idx[r]);
            float s = __ldg(&labels_scale[r]);
            size_t off = (size_t)r * (ZDIM / 4) + lane;
            float4 zvv = __ldcs(&z4[off]);
            float4 avv = __ldg(&at4[(size_t)i * (ZDIM / 4) + lane]);
            float4 o;
            o.x = fmaf(avv.x, s, zvv.x);
            o.y = fmaf(avv.y, s, zvv.y);
            o.z = fmaf(avv.z, s, zvv.z);
            o.w = fmaf(avv.w, s, zvv.w);
            __stcs(&out4[off], o);
        }
    }
}

extern "C" void kernel_launch(void* const* d_in, const int* in_sizes, int n_in,
                              void* d_out, int out_size) {
    const float* z     = (const float*)d_in[0];   // (B, 128) f32
    const float* a     = (const float*)d_in[1];   // (128, 512) f32
    const int*   idx   = (const int*)d_in[2];     // (B,) int32 on device
    const float* scale = (const float*)d_in[3];   // (B,) f32
    float*       out   = (float*)d_out;

    const int B = in_sizes[2];

    // 1) transpose a into L2-resident scratch (PDL producer)
    {
        dim3 grid(KDIM / 32, ZDIM / 32);   // (16, 4)
        dim3 block(32, 8);
        transpose_a_kernel<<<grid, block>>>(a);
    }

    // 2) fused gather + axpy, PDL consumer (overlaps the transpose)
    {
        int warps_per_block = 256 / 32;
        int rows_per_block  = warps_per_block * ROWS_PER_WARP;   // 64
        int blocks = (B + rows_per_block - 1) / rows_per_block;  // 16384

        cudaLaunchConfig_t cfg = {};
        cfg.gridDim  = dim3(blocks, 1, 1);
        cfg.blockDim = dim3(256, 1, 1);
        cfg.dynamicSmemBytes = 0;
        cfg.stream = 0;

        cudaLaunchAttribute attrs[1];
        attrs[0].id = cudaLaunchAttributeProgrammaticStreamSerialization;
        attrs[0].val.programmaticStreamSerializationAllowed = 1;
        cfg.attrs = attrs;
        cfg.numAttrs = 1;

        cudaLaunchKernelEx(&cfg, fused_gather_axpy_kernel,
                           (const float4*)z, idx, scale, (float4*)out, B);
    }
}